// round 4
// baseline (speedup 1.0000x reference)
#include <cuda_runtime.h>
#include <cuda_bf16.h>
#include <math.h>
#include <stdint.h>

#define S_LEN 2048
#define HID 1280
#define NH 16
#define HD 80
#define INTER 3420
#define NLAYER 8
#define WIN 64
#define MERGED 5120      // 4*HID
#define OUTDIM 3584
#define MTOK 512         // 2048/4

// ---------------- scratch (device globals; no allocation allowed) ----------------
__device__ float g_hs  [S_LEN * HID];
__device__ float g_x   [S_LEN * HID];
__device__ float g_qkv [S_LEN * 3 * HID];
__device__ float g_q   [NH * S_LEN * HD];
__device__ float g_k   [NH * S_LEN * HD];
__device__ float g_v   [NH * S_LEN * HD];
__device__ float g_att [S_LEN * HID];
__device__ float g_gate[S_LEN * INTER];
__device__ float g_fc1 [MTOK * MERGED];

// ---------------- elementwise kernels ----------------
__global__ void copy_k(const float* __restrict__ src, float* __restrict__ dst, int n) {
    int i = blockIdx.x * blockDim.x + threadIdx.x;
    if (i < n) dst[i] = src[i];
}

// RMSNorm: one block per row of 1280
__global__ void __launch_bounds__(256) rmsnorm_k(const float* __restrict__ x,
                                                 const float* __restrict__ w,
                                                 float* __restrict__ y) {
    int row = blockIdx.x;
    const float* xr = x + (long)row * HID;
    float ss = 0.f;
    for (int i = threadIdx.x; i < HID; i += 256) { float v = xr[i]; ss += v * v; }
    __shared__ float red[8];
    for (int o = 16; o > 0; o >>= 1) ss += __shfl_xor_sync(0xffffffffu, ss, o);
    if ((threadIdx.x & 31) == 0) red[threadIdx.x >> 5] = ss;
    __syncthreads();
    if (threadIdx.x < 32) {
        float v = (threadIdx.x < 8) ? red[threadIdx.x] : 0.f;
        for (int o = 4; o > 0; o >>= 1) v += __shfl_xor_sync(0xffffffffu, v, o);
        if (threadIdx.x == 0) red[0] = v;
    }
    __syncthreads();
    float inv = rsqrtf(red[0] / (float)HID + 1e-6f);
    for (int i = threadIdx.x; i < HID; i += 256)
        y[(long)row * HID + i] = xr[i] * inv * w[i];
}

// Split qkv [S, 3*HID] -> q,k,v [H,S,D] with RoPE on q,k
__global__ void rope_split_k(const float* __restrict__ qkv,
                             const float* __restrict__ cs,
                             const float* __restrict__ sn,
                             float* __restrict__ gq, float* __restrict__ gk,
                             float* __restrict__ gv) {
    int idx = blockIdx.x * blockDim.x + threadIdx.x;
    if (idx >= S_LEN * HID) return;
    int d = idx % HD;
    int h = (idx / HD) % NH;
    int s = idx / HID;
    const float* base = qkv + (long)s * (3 * HID);
    float c = cs[s * HD + d];
    float si = sn[s * HD + d];
    int f = h * HD + d;
    float qv = base[f];
    float kv = base[HID + f];
    float vv = base[2 * HID + f];
    int dr = (d < HD / 2) ? (d + HD / 2) : (d - HD / 2);
    float sgn = (d < HD / 2) ? -1.f : 1.f;
    float qr = sgn * base[h * HD + dr];
    float kr = sgn * base[HID + h * HD + dr];
    long o = ((long)h * S_LEN + s) * HD + d;
    gq[o] = qv * c + qr * si;
    gk[o] = kv * c + kr * si;
    gv[o] = vv;
}

// ---------------- flash attention (full or 64-window) ----------------
__global__ void __launch_bounds__(256) attn_k(const float* __restrict__ Q,
                                              const float* __restrict__ K,
                                              const float* __restrict__ V,
                                              const float* __restrict__ mask,
                                              int windowed,
                                              float* __restrict__ O) {
    __shared__ float Ks[64][HD];
    __shared__ float Vs[64][HD];
    int h = blockIdx.y;
    int q0 = blockIdx.x * 64;
    int tid = threadIdx.x;
    int qi = tid >> 2;
    int part = tid & 3;
    int d0 = part * 20;
    int q = q0 + qi;

    const float* Qb = Q + ((long)h * S_LEN + q) * HD;
    float qr[20];
#pragma unroll
    for (int i = 0; i < 20; ++i) qr[i] = Qb[d0 + i];

    float m = -3.0e38f, l = 0.f;
    float oacc[20];
#pragma unroll
    for (int i = 0; i < 20; ++i) oacc[i] = 0.f;

    int kvs = windowed ? q0 : 0;
    int kve = windowed ? q0 + 64 : S_LEN;
    const float scale = 0.11180339887498949f; // 1/sqrt(80)
    const float NEG = -3.0e38f;

    for (int kv0 = kvs; kv0 < kve; kv0 += 64) {
        __syncthreads();
        const float* Kb = K + ((long)h * S_LEN + kv0) * HD;
        const float* Vb = V + ((long)h * S_LEN + kv0) * HD;
        for (int i = tid; i < 64 * HD; i += 256) {
            Ks[i / HD][i % HD] = Kb[i];
            Vs[i / HD][i % HD] = Vb[i];
        }
        __syncthreads();
#pragma unroll 1
        for (int jc = 0; jc < 4; ++jc) {
            float sc[16];
#pragma unroll
            for (int jj = 0; jj < 16; ++jj) {
                int j = jc * 16 + jj;
                float a = 0.f;
#pragma unroll
                for (int dd = 0; dd < 20; ++dd) a += qr[dd] * Ks[j][d0 + dd];
                a += __shfl_xor_sync(0xffffffffu, a, 1);
                a += __shfl_xor_sync(0xffffffffu, a, 2);
                float mv;
                if (windowed)
                    mv = mask[(((long)(q0 >> 6) * 64 + qi) * 64) + j];
                else
                    mv = mask[(long)q * S_LEN + (kv0 + j)];
                sc[jj] = a * scale + (1.f - mv) * NEG;
            }
            float tmax = sc[0];
#pragma unroll
            for (int jj = 1; jj < 16; ++jj) tmax = fmaxf(tmax, sc[jj]);
            float mn = fmaxf(m, tmax);
            float corr = expf(m - mn);
#pragma unroll
            for (int dd = 0; dd < 20; ++dd) oacc[dd] *= corr;
            float ls = 0.f;
#pragma unroll
            for (int jj = 0; jj < 16; ++jj) {
                int j = jc * 16 + jj;
                float p = expf(sc[jj] - mn);
                ls += p;
#pragma unroll
                for (int dd = 0; dd < 20; ++dd) oacc[dd] += p * Vs[j][d0 + dd];
            }
            l = l * corr + ls;
            m = mn;
        }
    }
    float invl = 1.f / l;
#pragma unroll
    for (int dd = 0; dd < 20; ++dd)
        O[(long)q * HID + h * HD + d0 + dd] = oacc[dd] * invl;
}

// ---------------- 3xTF32 tensor-core GEMM, double-buffered, split-interleaved ----------------
// C[M,N] = epi(A[M,K] @ B[K,N] + bias)   (EPI: 0 none, 1 SiLU, 2 GELU, 3 += res, 4 *= res)
// Block 128x128xBK16, 256 thr (8 warps 2x4), warp tile 64x32, mma.m16n8k8.tf32.
// smem stores (big,small) tf32 pairs as float2: one LDS.64 per fragment element.
#define GBM 128
#define GBN 128
#define GBK 16
#define F2STR 132                      // float2 stride: 132 % 16 == 4 -> conflict-free frags
#define TILE_F2 (GBK * F2STR)          // one tile (A or B) in float2 units
#define STAGE_F2 (2 * TILE_F2)         // A + B
#define GEMM_SMEM_BYTES (2 * STAGE_F2 * sizeof(float2))   // 2 stages

__device__ __forceinline__ float tf32_big(float x) {
    uint32_t r;
    asm("cvt.rna.tf32.f32 %0, %1;" : "=r"(r) : "f"(x));
    return __uint_as_float(r);
}

__device__ __forceinline__ float2 split2(float x) {
    float b = tf32_big(x);
    return make_float2(b, tf32_big(x - b));
}

__device__ __forceinline__ void mma_tf32(float c[4], uint32_t a0, uint32_t a1,
                                         uint32_t a2, uint32_t a3,
                                         uint32_t b0, uint32_t b1) {
    asm volatile(
        "mma.sync.aligned.m16n8k8.row.col.f32.tf32.tf32.f32 "
        "{%0,%1,%2,%3}, {%4,%5,%6,%7}, {%8,%9}, {%0,%1,%2,%3};"
        : "+f"(c[0]), "+f"(c[1]), "+f"(c[2]), "+f"(c[3])
        : "r"(a0), "r"(a1), "r"(a2), "r"(a3), "r"(b0), "r"(b1));
}

template <int EPI>
__global__ void __launch_bounds__(256, 2) mmagemm_k(const float* __restrict__ A,
                                                    const float* __restrict__ B,
                                                    const float* __restrict__ bias,
                                                    const float* __restrict__ res,
                                                    float* __restrict__ C,
                                                    int M, int N, int K) {
    extern __shared__ float2 sm2[];

    int tid = threadIdx.x;
    int lane = tid & 31;
    int warp = tid >> 5;
    int warpM = warp & 1;
    int warpN = warp >> 1;
    int g = lane >> 2;
    int tg = lane & 3;

    int bmBase = blockIdx.y * GBM;
    int bnBase = blockIdx.x * GBN;

    float acc[4][4][4];
#pragma unroll
    for (int mi = 0; mi < 4; ++mi)
#pragma unroll
        for (int ni = 0; ni < 4; ++ni)
#pragma unroll
            for (int r = 0; r < 4; ++r) acc[mi][ni][r] = 0.f;

    // staging mappings
    int arow = tid & 127;              // A row within tile
    int ahalf = (tid >> 7) * 8;        // k offset (0 or 8), 8 k-values per thread
    const float* Aptr = A + (long)(bmBase + arow) * K + ahalf;
    int bk = tid >> 4;                 // k row 0..15
    int bn = (tid & 15) * 4;           // col 0..60 step 4 (also +64)

    int nk = (K + GBK - 1) / GBK;

    float4 av0, av1, bv0, bv1;

    auto ldg_tile = [&](int i) {
        int k0 = i * GBK;
        av0 = make_float4(0.f, 0.f, 0.f, 0.f);
        av1 = make_float4(0.f, 0.f, 0.f, 0.f);
        if (k0 + ahalf < K)     av0 = *(const float4*)(Aptr + k0);
        if (k0 + ahalf + 4 < K) av1 = *(const float4*)(Aptr + k0 + 4);
        bv0 = make_float4(0.f, 0.f, 0.f, 0.f);
        bv1 = make_float4(0.f, 0.f, 0.f, 0.f);
        if (k0 + bk < K) {
            const float* Bp = B + (long)(k0 + bk) * N + bnBase;
            if (bnBase + bn < N)      bv0 = *(const float4*)(Bp + bn);
            if (bnBase + bn + 64 < N) bv1 = *(const float4*)(Bp + bn + 64);
        }
    };

    auto sts_tile = [&](int s) {
        float2* As2 = sm2 + s * STAGE_F2;
        float2* Bs2 = As2 + TILE_F2;
        As2[(ahalf + 0) * F2STR + arow] = split2(av0.x);
        As2[(ahalf + 1) * F2STR + arow] = split2(av0.y);
        As2[(ahalf + 2) * F2STR + arow] = split2(av0.z);
        As2[(ahalf + 3) * F2STR + arow] = split2(av0.w);
        As2[(ahalf + 4) * F2STR + arow] = split2(av1.x);
        As2[(ahalf + 5) * F2STR + arow] = split2(av1.y);
        As2[(ahalf + 6) * F2STR + arow] = split2(av1.z);
        As2[(ahalf + 7) * F2STR + arow] = split2(av1.w);
        float2* Bp = Bs2 + bk * F2STR;
        Bp[bn + 0] = split2(bv0.x);
        Bp[bn + 1] = split2(bv0.y);
        Bp[bn + 2] = split2(bv0.z);
        Bp[bn + 3] = split2(bv0.w);
        Bp[bn + 64] = split2(bv1.x);
        Bp[bn + 65] = split2(bv1.y);
        Bp[bn + 66] = split2(bv1.z);
        Bp[bn + 67] = split2(bv1.w);
    };

    // prologue
    ldg_tile(0);
    sts_tile(0);
    if (nk > 1) ldg_tile(1);
    __syncthreads();

    for (int i = 0; i < nk; ++i) {
        int cur = i & 1;
        if (i + 1 < nk) sts_tile((i + 1) & 1);

        const float2* As2 = sm2 + cur * STAGE_F2;
        const float2* Bs2 = As2 + TILE_F2;

#pragma unroll
        for (int ks = 0; ks < GBK; ks += 8) {
            // B fragments: b0=(k tg, col g), b1=(k tg+4, col g)
            float2 bb[4][2];
#pragma unroll
            for (int ni = 0; ni < 4; ++ni) {
                int n = warpN * 32 + ni * 8 + g;
                bb[ni][0] = Bs2[(ks + tg) * F2STR + n];
                bb[ni][1] = Bs2[(ks + tg + 4) * F2STR + n];
            }
#pragma unroll
            for (int mi = 0; mi < 4; ++mi) {
                int m = warpM * 64 + mi * 16 + g;
                // a0=(g,tg) a1=(g+8,tg) a2=(g,tg+4) a3=(g+8,tg+4)
                float2 a0 = As2[(ks + tg) * F2STR + m];
                float2 a1 = As2[(ks + tg) * F2STR + m + 8];
                float2 a2 = As2[(ks + tg + 4) * F2STR + m];
                float2 a3 = As2[(ks + tg + 4) * F2STR + m + 8];
                uint32_t aB0 = __float_as_uint(a0.x), aB1 = __float_as_uint(a1.x);
                uint32_t aB2 = __float_as_uint(a2.x), aB3 = __float_as_uint(a3.x);
                uint32_t aS0 = __float_as_uint(a0.y), aS1 = __float_as_uint(a1.y);
                uint32_t aS2 = __float_as_uint(a2.y), aS3 = __float_as_uint(a3.y);
#pragma unroll
                for (int ni = 0; ni < 4; ++ni)
                    mma_tf32(acc[mi][ni], aB0, aB1, aB2, aB3,
                             __float_as_uint(bb[ni][0].x), __float_as_uint(bb[ni][1].x));
#pragma unroll
                for (int ni = 0; ni < 4; ++ni)
                    mma_tf32(acc[mi][ni], aB0, aB1, aB2, aB3,
                             __float_as_uint(bb[ni][0].y), __float_as_uint(bb[ni][1].y));
#pragma unroll
                for (int ni = 0; ni < 4; ++ni)
                    mma_tf32(acc[mi][ni], aS0, aS1, aS2, aS3,
                             __float_as_uint(bb[ni][0].x), __float_as_uint(bb[ni][1].x));
            }
        }

        if (i + 2 < nk) ldg_tile(i + 2);
        __syncthreads();
    }

    // ---- epilogue ----  c0=(g,2tg) c1=(g,2tg+1) c2=(g+8,2tg) c3=(g+8,2tg+1)
#pragma unroll
    for (int mi = 0; mi < 4; ++mi) {
        int row0 = bmBase + warpM * 64 + mi * 16 + g;
#pragma unroll
        for (int ni = 0; ni < 4; ++ni) {
            int col = bnBase + warpN * 32 + ni * 8 + 2 * tg;
            if (col >= N) continue;
            float b0 = bias[col], b1 = bias[col + 1];
#pragma unroll
            for (int rh = 0; rh < 2; ++rh) {
                int row = row0 + rh * 8;
                float v0 = acc[mi][ni][rh * 2 + 0] + b0;
                float v1 = acc[mi][ni][rh * 2 + 1] + b1;
                if (EPI == 1) {
                    v0 = v0 / (1.f + expf(-v0));
                    v1 = v1 / (1.f + expf(-v1));
                } else if (EPI == 2) {
                    v0 = 0.5f * v0 * (1.f + erff(v0 * 0.70710678118654752f));
                    v1 = 0.5f * v1 * (1.f + erff(v1 * 0.70710678118654752f));
                } else if (EPI == 3) {
                    v0 += res[(long)row * N + col];
                    v1 += res[(long)row * N + col + 1];
                } else if (EPI == 4) {
                    v0 *= res[(long)row * N + col];
                    v1 *= res[(long)row * N + col + 1];
                }
                C[(long)row * N + col] = v0;
                C[(long)row * N + col + 1] = v1;
            }
        }
    }
}

// ---------------- host ----------------
static inline dim3 gemm_grid(int M, int N) { return dim3((N + GBN - 1) / GBN, M / GBM); }

template <int EPI>
static void launch_gemm(const float* A, const float* B, const float* bias,
                        const float* res, float* C, int M, int N, int K) {
    static bool attr_done = false;
    if (!attr_done) {
        cudaFuncSetAttribute(mmagemm_k<EPI>, cudaFuncAttributeMaxDynamicSharedMemorySize,
                             (int)GEMM_SMEM_BYTES);
        attr_done = true;
    }
    mmagemm_k<EPI><<<gemm_grid(M, N), 256, GEMM_SMEM_BYTES>>>(A, B, bias, res, C, M, N, K);
}

extern "C" void kernel_launch(void* const* d_in, const int* in_sizes, int n_in,
                              void* d_out, int out_size) {
    const float* in_hs   = (const float*)d_in[0];
    const float* fmask   = (const float*)d_in[1];
    const float* wmask   = (const float*)d_in[2];
    const float* cosd    = (const float*)d_in[3];
    const float* sind    = (const float*)d_in[4];
    const float* norm1_w = (const float*)d_in[5];
    const float* norm2_w = (const float*)d_in[6];
    const float* qkv_w   = (const float*)d_in[7];
    const float* qkv_b   = (const float*)d_in[8];
    const float* proj_w  = (const float*)d_in[9];
    const float* proj_b  = (const float*)d_in[10];
    const float* gate_w  = (const float*)d_in[11];
    const float* gate_b  = (const float*)d_in[12];
    const float* up_w    = (const float*)d_in[13];
    const float* up_b    = (const float*)d_in[14];
    const float* down_w  = (const float*)d_in[15];
    const float* down_b  = (const float*)d_in[16];
    const float* ln_q_w  = (const float*)d_in[17];
    const float* fc1_w   = (const float*)d_in[18];
    const float* fc1_b   = (const float*)d_in[19];
    const float* fc2_w   = (const float*)d_in[20];
    const float* fc2_b   = (const float*)d_in[21];
    float* out = (float*)d_out;

    float *hs, *x, *qkv, *q, *k, *v, *att, *gate, *fc1;
    cudaGetSymbolAddress((void**)&hs, g_hs);
    cudaGetSymbolAddress((void**)&x, g_x);
    cudaGetSymbolAddress((void**)&qkv, g_qkv);
    cudaGetSymbolAddress((void**)&q, g_q);
    cudaGetSymbolAddress((void**)&k, g_k);
    cudaGetSymbolAddress((void**)&v, g_v);
    cudaGetSymbolAddress((void**)&att, g_att);
    cudaGetSymbolAddress((void**)&gate, g_gate);
    cudaGetSymbolAddress((void**)&fc1, g_fc1);

    const int nhid = S_LEN * HID;
    copy_k<<<(nhid + 255) / 256, 256>>>(in_hs, hs, nhid);

    for (int i = 0; i < NLAYER; ++i) {
        int full = (i == 3 || i == 7) ? 1 : 0;
        rmsnorm_k<<<S_LEN, 256>>>(hs, norm1_w + (long)i * HID, x);
        launch_gemm<0>(x, qkv_w + (long)i * HID * 3 * HID, qkv_b + (long)i * 3 * HID,
                       nullptr, qkv, S_LEN, 3 * HID, HID);
        rope_split_k<<<(nhid + 255) / 256, 256>>>(qkv, cosd, sind, q, k, v);
        attn_k<<<dim3(S_LEN / 64, NH), 256>>>(q, k, v, full ? fmask : wmask,
                                              full ? 0 : 1, att);
        launch_gemm<3>(att, proj_w + (long)i * HID * HID, proj_b + (long)i * HID,
                       hs, hs, S_LEN, HID, HID);
        rmsnorm_k<<<S_LEN, 256>>>(hs, norm2_w + (long)i * HID, x);
        launch_gemm<1>(x, gate_w + (long)i * HID * INTER, gate_b + (long)i * INTER,
                       nullptr, gate, S_LEN, INTER, HID);
        launch_gemm<4>(x, up_w + (long)i * HID * INTER, up_b + (long)i * INTER,
                       gate, gate, S_LEN, INTER, HID);
        launch_gemm<3>(gate, down_w + (long)i * INTER * HID, down_b + (long)i * HID,
                       hs, hs, S_LEN, HID, INTER);
    }

    // patch merger
    rmsnorm_k<<<S_LEN, 256>>>(hs, ln_q_w, x);  // x viewed as [512, 5120]
    launch_gemm<2>(x, fc1_w, fc1_b, nullptr, fc1, MTOK, MERGED, MERGED);
    launch_gemm<0>(fc1, fc2_w, fc2_b, nullptr, out, MTOK, OUTDIM, MERGED);
}

// round 5
// speedup vs baseline: 1.5430x; 1.5430x over previous
#include <cuda_runtime.h>
#include <cuda_bf16.h>
#include <math.h>
#include <stdint.h>

#define S_LEN 2048
#define HID 1280
#define NH 16
#define HD 80
#define INTER 3420
#define NLAYER 8
#define WIN 64
#define MERGED 5120      // 4*HID
#define OUTDIM 3584
#define MTOK 512         // 2048/4

// ---------------- scratch (device globals; no allocation allowed) ----------------
__device__ float g_hs  [S_LEN * HID];
__device__ float g_x   [S_LEN * HID];
__device__ float g_qkv [S_LEN * 3 * HID];
__device__ float g_q   [NH * S_LEN * HD];
__device__ float g_k   [NH * S_LEN * HD];
__device__ float g_v   [NH * S_LEN * HD];
__device__ float g_att [S_LEN * HID];
__device__ float g_gate[S_LEN * INTER];
__device__ float g_fc1 [MTOK * MERGED];

// ---------------- elementwise kernels ----------------
__global__ void copy_k(const float* __restrict__ src, float* __restrict__ dst, int n) {
    int i = blockIdx.x * blockDim.x + threadIdx.x;
    if (i < n) dst[i] = src[i];
}

// RMSNorm: one block per row of 1280
__global__ void __launch_bounds__(256) rmsnorm_k(const float* __restrict__ x,
                                                 const float* __restrict__ w,
                                                 float* __restrict__ y) {
    int row = blockIdx.x;
    const float* xr = x + (long)row * HID;
    float ss = 0.f;
    for (int i = threadIdx.x; i < HID; i += 256) { float v = xr[i]; ss += v * v; }
    __shared__ float red[8];
    for (int o = 16; o > 0; o >>= 1) ss += __shfl_xor_sync(0xffffffffu, ss, o);
    if ((threadIdx.x & 31) == 0) red[threadIdx.x >> 5] = ss;
    __syncthreads();
    if (threadIdx.x < 32) {
        float v = (threadIdx.x < 8) ? red[threadIdx.x] : 0.f;
        for (int o = 4; o > 0; o >>= 1) v += __shfl_xor_sync(0xffffffffu, v, o);
        if (threadIdx.x == 0) red[0] = v;
    }
    __syncthreads();
    float inv = rsqrtf(red[0] / (float)HID + 1e-6f);
    for (int i = threadIdx.x; i < HID; i += 256)
        y[(long)row * HID + i] = xr[i] * inv * w[i];
}

// Split qkv [S, 3*HID] -> q,k,v [H,S,D] with RoPE on q,k
__global__ void rope_split_k(const float* __restrict__ qkv,
                             const float* __restrict__ cs,
                             const float* __restrict__ sn,
                             float* __restrict__ gq, float* __restrict__ gk,
                             float* __restrict__ gv) {
    int idx = blockIdx.x * blockDim.x + threadIdx.x;
    if (idx >= S_LEN * HID) return;
    int d = idx % HD;
    int h = (idx / HD) % NH;
    int s = idx / HID;
    const float* base = qkv + (long)s * (3 * HID);
    float c = cs[s * HD + d];
    float si = sn[s * HD + d];
    int f = h * HD + d;
    float qv = base[f];
    float kv = base[HID + f];
    float vv = base[2 * HID + f];
    int dr = (d < HD / 2) ? (d + HD / 2) : (d - HD / 2);
    float sgn = (d < HD / 2) ? -1.f : 1.f;
    float qr = sgn * base[h * HD + dr];
    float kr = sgn * base[HID + h * HD + dr];
    long o = ((long)h * S_LEN + s) * HD + d;
    gq[o] = qv * c + qr * si;
    gk[o] = kv * c + kr * si;
    gv[o] = vv;
}

// ---------------- flash attention (full or 64-window) ----------------
__global__ void __launch_bounds__(256) attn_k(const float* __restrict__ Q,
                                              const float* __restrict__ K,
                                              const float* __restrict__ V,
                                              const float* __restrict__ mask,
                                              int windowed,
                                              float* __restrict__ O) {
    __shared__ float Ks[64][HD];
    __shared__ float Vs[64][HD];
    int h = blockIdx.y;
    int q0 = blockIdx.x * 64;
    int tid = threadIdx.x;
    int qi = tid >> 2;
    int part = tid & 3;
    int d0 = part * 20;
    int q = q0 + qi;

    const float* Qb = Q + ((long)h * S_LEN + q) * HD;
    float qr[20];
#pragma unroll
    for (int i = 0; i < 20; ++i) qr[i] = Qb[d0 + i];

    float m = -3.0e38f, l = 0.f;
    float oacc[20];
#pragma unroll
    for (int i = 0; i < 20; ++i) oacc[i] = 0.f;

    int kvs = windowed ? q0 : 0;
    int kve = windowed ? q0 + 64 : S_LEN;
    const float scale = 0.11180339887498949f; // 1/sqrt(80)
    const float NEG = -3.0e38f;

    for (int kv0 = kvs; kv0 < kve; kv0 += 64) {
        __syncthreads();
        const float* Kb = K + ((long)h * S_LEN + kv0) * HD;
        const float* Vb = V + ((long)h * S_LEN + kv0) * HD;
        for (int i = tid; i < 64 * HD; i += 256) {
            Ks[i / HD][i % HD] = Kb[i];
            Vs[i / HD][i % HD] = Vb[i];
        }
        __syncthreads();
#pragma unroll 1
        for (int jc = 0; jc < 4; ++jc) {
            float sc[16];
#pragma unroll
            for (int jj = 0; jj < 16; ++jj) {
                int j = jc * 16 + jj;
                float a = 0.f;
#pragma unroll
                for (int dd = 0; dd < 20; ++dd) a += qr[dd] * Ks[j][d0 + dd];
                a += __shfl_xor_sync(0xffffffffu, a, 1);
                a += __shfl_xor_sync(0xffffffffu, a, 2);
                float mv;
                if (windowed)
                    mv = mask[(((long)(q0 >> 6) * 64 + qi) * 64) + j];
                else
                    mv = mask[(long)q * S_LEN + (kv0 + j)];
                sc[jj] = a * scale + (1.f - mv) * NEG;
            }
            float tmax = sc[0];
#pragma unroll
            for (int jj = 1; jj < 16; ++jj) tmax = fmaxf(tmax, sc[jj]);
            float mn = fmaxf(m, tmax);
            float corr = expf(m - mn);
#pragma unroll
            for (int dd = 0; dd < 20; ++dd) oacc[dd] *= corr;
            float ls = 0.f;
#pragma unroll
            for (int jj = 0; jj < 16; ++jj) {
                int j = jc * 16 + jj;
                float p = expf(sc[jj] - mn);
                ls += p;
#pragma unroll
                for (int dd = 0; dd < 20; ++dd) oacc[dd] += p * Vs[j][d0 + dd];
            }
            l = l * corr + ls;
            m = mn;
        }
    }
    float invl = 1.f / l;
#pragma unroll
    for (int dd = 0; dd < 20; ++dd)
        O[(long)q * HID + h * HD + d0 + dd] = oacc[dd] * invl;
}

// ---------------- bf16x3-split tensor-core GEMM (m16n8k16) ----------------
// C[M,N] = epi(A[M,K] @ B[K,N] + bias)   (EPI: 0 none, 1 SiLU, 2 GELU, 3 += res, 4 *= res)
// Block 128x128xBK16, 256 thr (8 warps 2x4), warp tile 64x32.
// Each fp32 split big+small bf16; acc += Ab*Bb + Ab*Bs + As*Bb.
// smem holds packed bf16x2 (pairs along k) -> 48 LDS + 48 MMA per warp per tile.
#define GBM 128
#define GBN 128
#define GBK 16
#define USTR 136   // uint32 row stride: banks (8*tg + g) all distinct

__device__ __forceinline__ void split_bf16(float x, uint16_t& b, uint16_t& s) {
    __nv_bfloat16 hb = __float2bfloat16(x);
    float r = x - __bfloat162float(hb);
    __nv_bfloat16 hs = __float2bfloat16(r);
    b = *(uint16_t*)&hb;
    s = *(uint16_t*)&hs;
}

// pack two bf16 (k even in low bits, k odd in high bits)
__device__ __forceinline__ void pack_pair(float lo, float hi, uint32_t& big, uint32_t& sml) {
    uint16_t bl, sl, bh, sh;
    split_bf16(lo, bl, sl);
    split_bf16(hi, bh, sh);
    big = (uint32_t)bl | ((uint32_t)bh << 16);
    sml = (uint32_t)sl | ((uint32_t)sh << 16);
}

__device__ __forceinline__ void mma_bf16(float c[4], uint32_t a0, uint32_t a1,
                                         uint32_t a2, uint32_t a3,
                                         uint32_t b0, uint32_t b1) {
    asm volatile(
        "mma.sync.aligned.m16n8k16.row.col.f32.bf16.bf16.f32 "
        "{%0,%1,%2,%3}, {%4,%5,%6,%7}, {%8,%9}, {%0,%1,%2,%3};"
        : "+f"(c[0]), "+f"(c[1]), "+f"(c[2]), "+f"(c[3])
        : "r"(a0), "r"(a1), "r"(a2), "r"(a3), "r"(b0), "r"(b1));
}

template <int EPI>
__global__ void __launch_bounds__(256, 2) mmagemm_k(const float* __restrict__ A,
                                                    const float* __restrict__ B,
                                                    const float* __restrict__ bias,
                                                    const float* __restrict__ res,
                                                    float* __restrict__ C,
                                                    int M, int N, int K) {
    // 8 k-pairs per tile (BK=16)
    __shared__ uint32_t AsB[8][USTR];
    __shared__ uint32_t AsS[8][USTR];
    __shared__ uint32_t BsB[8][USTR];
    __shared__ uint32_t BsS[8][USTR];

    int tid = threadIdx.x;
    int lane = tid & 31;
    int warp = tid >> 5;
    int warpM = warp & 1;     // 64-row half
    int warpN = warp >> 1;    // 32-col quarter
    int g = lane >> 2;        // 0..7
    int tg = lane & 3;        // 0..3

    int bmBase = blockIdx.y * GBM;
    int bnBase = blockIdx.x * GBN;

    float acc[4][4][4];
#pragma unroll
    for (int mi = 0; mi < 4; ++mi)
#pragma unroll
        for (int ni = 0; ni < 4; ++ni)
#pragma unroll
            for (int r = 0; r < 4; ++r) acc[mi][ni][r] = 0.f;

    // A staging: thread -> row = tid&127, k-half = (tid>>7)*8 (8 k = 4 pairs)
    int arow = tid & 127;
    int ahalf = (tid >> 7) * 8;
    int apair = ahalf >> 1;             // 0 or 4
    const float* Aptr = A + (long)(bmBase + arow) * K + ahalf;
    // B staging: thread -> pair = tid>>5 (0..7), col4 = (tid&31)*4
    int bpair = tid >> 5;
    int bcol = (tid & 31) * 4;
    int gbcol = bnBase + bcol;

    for (int k0 = 0; k0 < K; k0 += GBK) {
        // ---- stage A (8 k values -> 4 packed pairs big+small) ----
        float a[8];
        if (k0 + GBK <= K) {
            float4 v0 = *(const float4*)(Aptr + k0);
            float4 v1 = *(const float4*)(Aptr + k0 + 4);
            a[0] = v0.x; a[1] = v0.y; a[2] = v0.z; a[3] = v0.w;
            a[4] = v1.x; a[5] = v1.y; a[6] = v1.z; a[7] = v1.w;
        } else {
#pragma unroll
            for (int t = 0; t < 8; ++t) {
                int kk = k0 + ahalf + t;
                a[t] = (kk < K) ? Aptr[k0 + t] : 0.f;
            }
        }
#pragma unroll
        for (int p = 0; p < 4; ++p) {
            uint32_t big, sml;
            pack_pair(a[2 * p], a[2 * p + 1], big, sml);
            AsB[apair + p][arow] = big;
            AsS[apair + p][arow] = sml;
        }
        // ---- stage B (2 k-rows x 4 cols -> 4 packed pairs big+small) ----
        {
            int kr0 = k0 + 2 * bpair;
            float e0[4], e1[4];
            if (kr0 + 1 < K && gbcol + 3 < N) {
                float4 v0 = *(const float4*)(B + (long)kr0 * N + gbcol);
                float4 v1 = *(const float4*)(B + (long)(kr0 + 1) * N + gbcol);
                e0[0] = v0.x; e0[1] = v0.y; e0[2] = v0.z; e0[3] = v0.w;
                e1[0] = v1.x; e1[1] = v1.y; e1[2] = v1.z; e1[3] = v1.w;
            } else {
#pragma unroll
                for (int c = 0; c < 4; ++c) {
                    int col = gbcol + c;
                    e0[c] = (kr0 < K && col < N) ? B[(long)kr0 * N + col] : 0.f;
                    e1[c] = (kr0 + 1 < K && col < N) ? B[(long)(kr0 + 1) * N + col] : 0.f;
                }
            }
#pragma unroll
            for (int c = 0; c < 4; ++c) {
                uint32_t big, sml;
                pack_pair(e0[c], e1[c], big, sml);
                BsB[bpair][bcol + c] = big;
                BsS[bpair][bcol + c] = sml;
            }
        }
        __syncthreads();

        // ---- compute: one m16n8k16 chunk per tile ----
        // a0=(g, pair tg) a1=(g+8, pair tg) a2=(g, pair tg+4) a3=(g+8, pair tg+4)
        // b0=(pair tg, col g) b1=(pair tg+4, col g)
        uint32_t bB[4][2], bS[4][2];
#pragma unroll
        for (int ni = 0; ni < 4; ++ni) {
            int n = warpN * 32 + ni * 8 + g;
            bB[ni][0] = BsB[tg][n];
            bB[ni][1] = BsB[tg + 4][n];
            bS[ni][0] = BsS[tg][n];
            bS[ni][1] = BsS[tg + 4][n];
        }
#pragma unroll
        for (int mi = 0; mi < 4; ++mi) {
            int m = warpM * 64 + mi * 16 + g;
            uint32_t aB0 = AsB[tg][m], aB1 = AsB[tg][m + 8];
            uint32_t aB2 = AsB[tg + 4][m], aB3 = AsB[tg + 4][m + 8];
            uint32_t aS0 = AsS[tg][m], aS1 = AsS[tg][m + 8];
            uint32_t aS2 = AsS[tg + 4][m], aS3 = AsS[tg + 4][m + 8];
#pragma unroll
            for (int ni = 0; ni < 4; ++ni)
                mma_bf16(acc[mi][ni], aB0, aB1, aB2, aB3, bB[ni][0], bB[ni][1]);
#pragma unroll
            for (int ni = 0; ni < 4; ++ni)
                mma_bf16(acc[mi][ni], aB0, aB1, aB2, aB3, bS[ni][0], bS[ni][1]);
#pragma unroll
            for (int ni = 0; ni < 4; ++ni)
                mma_bf16(acc[mi][ni], aS0, aS1, aS2, aS3, bB[ni][0], bB[ni][1]);
        }
        __syncthreads();
    }

    // ---- epilogue ----  c0=(g,2tg) c1=(g,2tg+1) c2=(g+8,2tg) c3=(g+8,2tg+1)
#pragma unroll
    for (int mi = 0; mi < 4; ++mi) {
        int row0 = bmBase + warpM * 64 + mi * 16 + g;
#pragma unroll
        for (int ni = 0; ni < 4; ++ni) {
            int col = bnBase + warpN * 32 + ni * 8 + 2 * tg;
            if (col >= N) continue;
            float b0 = bias[col], b1 = bias[col + 1];
#pragma unroll
            for (int rh = 0; rh < 2; ++rh) {
                int row = row0 + rh * 8;
                float v0 = acc[mi][ni][rh * 2 + 0] + b0;
                float v1 = acc[mi][ni][rh * 2 + 1] + b1;
                if (EPI == 1) {
                    v0 = v0 / (1.f + expf(-v0));
                    v1 = v1 / (1.f + expf(-v1));
                } else if (EPI == 2) {
                    v0 = 0.5f * v0 * (1.f + erff(v0 * 0.70710678118654752f));
                    v1 = 0.5f * v1 * (1.f + erff(v1 * 0.70710678118654752f));
                } else if (EPI == 3) {
                    v0 += res[(long)row * N + col];
                    v1 += res[(long)row * N + col + 1];
                } else if (EPI == 4) {
                    v0 *= res[(long)row * N + col];
                    v1 *= res[(long)row * N + col + 1];
                }
                C[(long)row * N + col] = v0;
                C[(long)row * N + col + 1] = v1;
            }
        }
    }
}

// ---------------- host ----------------
static inline dim3 gemm_grid(int M, int N) { return dim3((N + GBN - 1) / GBN, M / GBM); }

extern "C" void kernel_launch(void* const* d_in, const int* in_sizes, int n_in,
                              void* d_out, int out_size) {
    const float* in_hs   = (const float*)d_in[0];
    const float* fmask   = (const float*)d_in[1];
    const float* wmask   = (const float*)d_in[2];
    const float* cosd    = (const float*)d_in[3];
    const float* sind    = (const float*)d_in[4];
    const float* norm1_w = (const float*)d_in[5];
    const float* norm2_w = (const float*)d_in[6];
    const float* qkv_w   = (const float*)d_in[7];
    const float* qkv_b   = (const float*)d_in[8];
    const float* proj_w  = (const float*)d_in[9];
    const float* proj_b  = (const float*)d_in[10];
    const float* gate_w  = (const float*)d_in[11];
    const float* gate_b  = (const float*)d_in[12];
    const float* up_w    = (const float*)d_in[13];
    const float* up_b    = (const float*)d_in[14];
    const float* down_w  = (const float*)d_in[15];
    const float* down_b  = (const float*)d_in[16];
    const float* ln_q_w  = (const float*)d_in[17];
    const float* fc1_w   = (const float*)d_in[18];
    const float* fc1_b   = (const float*)d_in[19];
    const float* fc2_w   = (const float*)d_in[20];
    const float* fc2_b   = (const float*)d_in[21];
    float* out = (float*)d_out;

    float *hs, *x, *qkv, *q, *k, *v, *att, *gate, *fc1;
    cudaGetSymbolAddress((void**)&hs, g_hs);
    cudaGetSymbolAddress((void**)&x, g_x);
    cudaGetSymbolAddress((void**)&qkv, g_qkv);
    cudaGetSymbolAddress((void**)&q, g_q);
    cudaGetSymbolAddress((void**)&k, g_k);
    cudaGetSymbolAddress((void**)&v, g_v);
    cudaGetSymbolAddress((void**)&att, g_att);
    cudaGetSymbolAddress((void**)&gate, g_gate);
    cudaGetSymbolAddress((void**)&fc1, g_fc1);

    const int nhid = S_LEN * HID;
    copy_k<<<(nhid + 255) / 256, 256>>>(in_hs, hs, nhid);

    for (int i = 0; i < NLAYER; ++i) {
        int full = (i == 3 || i == 7) ? 1 : 0;
        rmsnorm_k<<<S_LEN, 256>>>(hs, norm1_w + (long)i * HID, x);
        mmagemm_k<0><<<gemm_grid(S_LEN, 3 * HID), 256>>>(
            x, qkv_w + (long)i * HID * 3 * HID, qkv_b + (long)i * 3 * HID,
            nullptr, qkv, S_LEN, 3 * HID, HID);
        rope_split_k<<<(nhid + 255) / 256, 256>>>(qkv, cosd, sind, q, k, v);
        attn_k<<<dim3(S_LEN / 64, NH), 256>>>(q, k, v, full ? fmask : wmask,
                                              full ? 0 : 1, att);
        mmagemm_k<3><<<gemm_grid(S_LEN, HID), 256>>>(
            att, proj_w + (long)i * HID * HID, proj_b + (long)i * HID,
            hs, hs, S_LEN, HID, HID);
        rmsnorm_k<<<S_LEN, 256>>>(hs, norm2_w + (long)i * HID, x);
        mmagemm_k<1><<<gemm_grid(S_LEN, INTER), 256>>>(
            x, gate_w + (long)i * HID * INTER, gate_b + (long)i * INTER,
            nullptr, gate, S_LEN, INTER, HID);
        mmagemm_k<4><<<gemm_grid(S_LEN, INTER), 256>>>(
            x, up_w + (long)i * HID * INTER, up_b + (long)i * INTER,
            gate, gate, S_LEN, INTER, HID);
        mmagemm_k<3><<<gemm_grid(S_LEN, HID), 256>>>(
            gate, down_w + (long)i * INTER * HID, down_b + (long)i * HID,
            hs, hs, S_LEN, HID, INTER);
    }

    // patch merger
    rmsnorm_k<<<S_LEN, 256>>>(hs, ln_q_w, x);  // x viewed as [512, 5120]
    mmagemm_k<2><<<gemm_grid(MTOK, MERGED), 256>>>(
        x, fc1_w, fc1_b, nullptr, fc1, MTOK, MERGED, MERGED);
    mmagemm_k<0><<<gemm_grid(MTOK, OUTDIM), 256>>>(
        fc1, fc2_w, fc2_b, nullptr, out, MTOK, OUTDIM, MERGED);
}